// round 1
// baseline (speedup 1.0000x reference)
#include <cuda_runtime.h>
#include <math_constants.h>

// Problem constants
#define NN      8192
#define IN_DIM  200
#define DD      64
#define BM      64
#define BN      64
#define NTHREADS 256
#define PAD     68          // row stride (floats): multiple of 4 for float4, odd/32 enough
#define NEG_BIG (-1.0e9f)

// Scratch: H = X@W + b  (8192 x 64 fp32 = 2 MB, L2-resident)
__device__ float g_H[NN * DD];

// ---------------------------------------------------------------------------
// Kernel 1: H = X @ W + b.  256 threads -> 4 rows x 64 dims per block.
// X row elements broadcast via L1, W column reads coalesced across dim.
// ---------------------------------------------------------------------------
__global__ void h_kernel(const float* __restrict__ X,
                         const float* __restrict__ W,
                         const float* __restrict__ b) {
    int row = blockIdx.x * 4 + (threadIdx.x >> 6);
    int d   = threadIdx.x & 63;
    const float* x = X + (size_t)row * IN_DIM;
    float acc = b[d];
#pragma unroll 10
    for (int k = 0; k < IN_DIM; k++)
        acc = fmaf(x[k], W[k * DD + d], acc);
    g_H[row * DD + d] = acc;
}

// ---------------------------------------------------------------------------
// Kernel 2: fused masked attention (flash style).
// Each block: 64 query rows. Loop over 128 key tiles of 64 keys.
// Thread (ty,tx) in 16x16 grid owns a 4x4 register tile.
// ---------------------------------------------------------------------------
__global__ __launch_bounds__(NTHREADS, 1)
void flash_kernel(const int* __restrict__ A, float* __restrict__ Out) {
    extern __shared__ float smem[];
    float* sQ  = smem;                 // [DD][PAD]  dim-major:  sQ[d][row]
    float* sK  = sQ  + DD * PAD;       // [DD][PAD]  dim-major:  sK[d][key]
    float* sKn = sK  + DD * PAD;       // [BN][PAD]  key-major:  sKn[key][d]
    float* sP  = sKn + BN * PAD;       // [BN][PAD]  P^T:        sP[key][row]

    const int tid   = threadIdx.x;
    const int tx    = tid & 15;        // 16 col-groups (keys in S, dims in O)
    const int ty    = tid >> 4;        // 16 row-groups (query rows)
    const int qbase = blockIdx.x * BM;

    // Load Q tile transposed (dim-major). Conflict-free: lane stride = PAD.
    for (int i = tid; i < BM * DD; i += NTHREADS) {
        int r = i >> 6, d = i & 63;
        sQ[d * PAD + r] = g_H[(qbase + r) * DD + d];
    }

    float m[4], l[4], acc[4][4];
#pragma unroll
    for (int r = 0; r < 4; r++) {
        m[r] = -CUDART_INF_F;
        l[r] = 0.0f;
#pragma unroll
        for (int c = 0; c < 4; c++) acc[r][c] = 0.0f;
    }
    __syncthreads();

    for (int kb = 0; kb < NN; kb += BN) {
        // --- K tile load: one global read, two shared layouts ---
        for (int i = tid; i < BN * DD; i += NTHREADS) {
            int kk = i >> 6, d = i & 63;
            float v = g_H[(kb + kk) * DD + d];
            sK[d * PAD + kk]  = v;     // dim-major (for S = Q K^T)
            sKn[kk * PAD + d] = v;     // key-major (for O = P K)
        }
        // --- Adjacency prefetch: the only mandatory HBM traffic ---
        int4 am[4];
#pragma unroll
        for (int r = 0; r < 4; r++)
            am[r] = *(const int4*)(A + (size_t)(qbase + ty * 4 + r) * NN + kb + tx * 4);
        __syncthreads();

        // --- S = Q K^T : 4x4 register tile, float4 shared reads ---
        float s[4][4];
#pragma unroll
        for (int r = 0; r < 4; r++)
#pragma unroll
            for (int c = 0; c < 4; c++) s[r][c] = 0.0f;

#pragma unroll 8
        for (int k = 0; k < DD; k++) {
            float4 aq = *(const float4*)&sQ[k * PAD + ty * 4];
            float4 bk = *(const float4*)&sK[k * PAD + tx * 4];
            float aqa[4] = {aq.x, aq.y, aq.z, aq.w};
            float bka[4] = {bk.x, bk.y, bk.z, bk.w};
#pragma unroll
            for (int r = 0; r < 4; r++)
#pragma unroll
                for (int c = 0; c < 4; c++)
                    s[r][c] = fmaf(aqa[r], bka[c], s[r][c]);
        }

        // --- mask ---
#pragma unroll
        for (int r = 0; r < 4; r++) {
            s[r][0] = (am[r].x > 0) ? s[r][0] : NEG_BIG;
            s[r][1] = (am[r].y > 0) ? s[r][1] : NEG_BIG;
            s[r][2] = (am[r].z > 0) ? s[r][2] : NEG_BIG;
            s[r][3] = (am[r].w > 0) ? s[r][3] : NEG_BIG;
        }

        // --- online softmax: rowmax over 64 keys (local + shfl over 16 lanes) ---
        float mt[4];
#pragma unroll
        for (int r = 0; r < 4; r++)
            mt[r] = fmaxf(fmaxf(s[r][0], s[r][1]), fmaxf(s[r][2], s[r][3]));
#pragma unroll
        for (int o = 8; o >= 1; o >>= 1)
#pragma unroll
            for (int r = 0; r < 4; r++)
                mt[r] = fmaxf(mt[r], __shfl_xor_sync(0xffffffffu, mt[r], o));

        float scale[4];
#pragma unroll
        for (int r = 0; r < 4; r++) {
            float mnew = fmaxf(m[r], mt[r]);
            scale[r] = __expf(m[r] - mnew);   // exp(-inf)=0 handles first tile
            m[r] = mnew;
        }

        float p[4][4], psum[4];
#pragma unroll
        for (int r = 0; r < 4; r++) {
            psum[r] = 0.0f;
#pragma unroll
            for (int c = 0; c < 4; c++) {
                p[r][c] = __expf(s[r][c] - m[r]);
                psum[r] += p[r][c];
            }
        }
#pragma unroll
        for (int o = 8; o >= 1; o >>= 1)
#pragma unroll
            for (int r = 0; r < 4; r++)
                psum[r] += __shfl_xor_sync(0xffffffffu, psum[r], o);

#pragma unroll
        for (int r = 0; r < 4; r++) {
            l[r] = l[r] * scale[r] + psum[r];
#pragma unroll
            for (int c = 0; c < 4; c++) acc[r][c] *= scale[r];
        }

        // --- stage P^T to shared: sP[key][row], aligned float4 stores ---
#pragma unroll
        for (int c = 0; c < 4; c++) {
            float4 v = make_float4(p[0][c], p[1][c], p[2][c], p[3][c]);
            *(float4*)&sP[(tx * 4 + c) * PAD + ty * 4] = v;
        }
        __syncthreads();

        // --- O += P K : same 4x4 register-tile structure ---
#pragma unroll 8
        for (int k = 0; k < BN; k++) {
            float4 rp = *(const float4*)&sP[k * PAD + ty * 4];
            float4 hv = *(const float4*)&sKn[k * PAD + tx * 4];
            float rpa[4] = {rp.x, rp.y, rp.z, rp.w};
            float hva[4] = {hv.x, hv.y, hv.z, hv.w};
#pragma unroll
            for (int r = 0; r < 4; r++)
#pragma unroll
                for (int c = 0; c < 4; c++)
                    acc[r][c] = fmaf(rpa[r], hva[c], acc[r][c]);
        }
        __syncthreads();   // protects sP and sKn for next tile
    }

    // --- epilogue: normalize, relu, store ---
#pragma unroll
    for (int r = 0; r < 4; r++) {
        float inv = 1.0f / l[r];
        float4 o;
        o.x = fmaxf(acc[r][0] * inv, 0.0f);
        o.y = fmaxf(acc[r][1] * inv, 0.0f);
        o.z = fmaxf(acc[r][2] * inv, 0.0f);
        o.w = fmaxf(acc[r][3] * inv, 0.0f);
        *(float4*)&Out[(size_t)(qbase + ty * 4 + r) * DD + tx * 4] = o;
    }
}

// ---------------------------------------------------------------------------
extern "C" void kernel_launch(void* const* d_in, const int* in_sizes, int n_in,
                              void* d_out, int out_size) {
    const float* X = (const float*)d_in[0];
    const int*   A = (const int*)  d_in[1];
    const float* W = (const float*)d_in[2];
    const float* b = (const float*)d_in[3];
    float* Out = (float*)d_out;

    static bool attr_set = false;
    const int smem_bytes = 4 * DD * PAD * sizeof(float);  // 69632 B
    if (!attr_set) {
        cudaFuncSetAttribute(flash_kernel,
                             cudaFuncAttributeMaxDynamicSharedMemorySize,
                             smem_bytes);
        attr_set = true;
    }

    h_kernel<<<NN / 4, NTHREADS>>>(X, W, b);
    flash_kernel<<<NN / BM, NTHREADS, smem_bytes>>>(A, Out);
}

// round 2
// speedup vs baseline: 1.6099x; 1.6099x over previous
#include <cuda_runtime.h>
#include <math_constants.h>

#define NN       8192
#define IN_DIM   200
#define DD       64
#define BM       64
#define BN       64
#define NT       256
#define STR      68            // smem row stride in floats (even, conflict-light)
#define NEG_BIG  (-1.0e9f)

// Scratch: H = X@W + b (8192 x 64 fp32 = 2 MB, L2-resident)
__device__ float g_H[NN * DD];

// ---------------------------------------------------------------------------
__device__ __forceinline__ unsigned f2tf32(float f) {
    unsigned r;
    asm("cvt.rna.tf32.f32 %0, %1;" : "=r"(r) : "f"(f));
    return r;
}

// k-pair interleave within 8-blocks: (k, k+4) land adjacent -> 1x LDS.64/frag
__device__ __forceinline__ int perm8(int j) { return ((j & 3) << 1) | (j >> 2); }
__device__ __forceinline__ int perm (int j) { return (j & ~7) | perm8(j & 7); }

__device__ __forceinline__ void mma_tf32(float c[4],
                                         unsigned a0, unsigned a1,
                                         unsigned a2, unsigned a3,
                                         unsigned b0, unsigned b1) {
    asm volatile(
        "mma.sync.aligned.m16n8k8.row.col.f32.tf32.tf32.f32 "
        "{%0,%1,%2,%3}, {%4,%5,%6,%7}, {%8,%9}, {%0,%1,%2,%3};"
        : "+f"(c[0]), "+f"(c[1]), "+f"(c[2]), "+f"(c[3])
        : "r"(a0), "r"(a1), "r"(a2), "r"(a3), "r"(b0), "r"(b1));
}

// ---------------------------------------------------------------------------
// Kernel 1: H = X @ W + b
// ---------------------------------------------------------------------------
__global__ void h_kernel(const float* __restrict__ X,
                         const float* __restrict__ W,
                         const float* __restrict__ b) {
    int row = blockIdx.x * 4 + (threadIdx.x >> 6);
    int d   = threadIdx.x & 63;
    const float* x = X + (size_t)row * IN_DIM;
    float acc = b[d];
#pragma unroll 10
    for (int k = 0; k < IN_DIM; k++)
        acc = fmaf(x[k], W[k * DD + d], acc);
    g_H[row * DD + d] = acc;
}

// ---------------------------------------------------------------------------
// Kernel 2: fused masked flash attention on mma.sync tf32 tensor cores.
// 8 warps: wm in 0..3 (16 query rows each), wn in 0..1 (32 cols each).
// ---------------------------------------------------------------------------
__global__ __launch_bounds__(NT, 1)
void flash_mma(const int* __restrict__ A, float* __restrict__ Out) {
    extern __shared__ float sm[];
    float* sK  = sm;                 // [BN][STR]  B-frags for S: n=key, k=dim (perm)
    float* sV  = sK  + BN * STR;     // [DD][STR]  B-frags for O: n=dim, k=key (perm^xor)
    float* sSP = sV  + DD * STR;     // [BM][STR]  masked S, then P (A-frag perm)
    float* sScale = sSP + BM * STR;  // [64]
    float* sL     = sScale + 64;     // [64]

    const int tid  = threadIdx.x;
    const int lane = tid & 31;
    const int wid  = tid >> 5;
    const int wm   = wid >> 1;       // 0..3
    const int wn   = wid & 1;        // 0..1
    const int lr   = lane >> 2;      // 0..7
    const int lc   = lane & 3;       // 0..3
    const int qbase = blockIdx.x * BM;

    // ---- Q fragments in registers (rows wm*16 + lr (+8), all 64 dims) ----
    unsigned aQ[8][4];
    {
        const int r0 = qbase + wm * 16 + lr;
#pragma unroll
        for (int ks = 0; ks < 8; ks++) {
            int c0 = ks * 8 + lc;
            aQ[ks][0] = f2tf32(g_H[(size_t)r0 * DD + c0]);
            aQ[ks][1] = f2tf32(g_H[(size_t)(r0 + 8) * DD + c0]);
            aQ[ks][2] = f2tf32(g_H[(size_t)r0 * DD + c0 + 4]);
            aQ[ks][3] = f2tf32(g_H[(size_t)(r0 + 8) * DD + c0 + 4]);
        }
    }

    float oc[4][4];
#pragma unroll
    for (int na = 0; na < 4; na++)
#pragma unroll
        for (int j = 0; j < 4; j++) oc[na][j] = 0.0f;

    // softmax state: thread tid owns row tid>>2, cols 16*(tid&3)..+15
    const int srow  = tid >> 2;
    const int scol0 = (tid & 3) << 4;
    float mrow = -CUDART_INF_F, lrow = 0.0f;

    const int lrow0 = wm * 16 + lr;          // mma-local row
    const int grow0 = qbase + lrow0;

    for (int kb = 0; kb < NN; kb += BN) {
        // ---- adjacency prefetch (the DRAM stream) ----
        int2 am[4][2];
#pragma unroll
        for (int na = 0; na < 4; na++) {
            int col = kb + wn * 32 + na * 8 + 2 * lc;
            am[na][0] = *(const int2*)(A + (size_t)grow0 * NN + col);
            am[na][1] = *(const int2*)(A + (size_t)(grow0 + 8) * NN + col);
        }

        // ---- stage K tile into both fragment layouts (tf32) ----
#pragma unroll
        for (int ii = 0; ii < 4; ii++) {
            int i   = tid + ii * NT;         // float4 index
            int key = i >> 4;
            int d4  = (i & 15) * 4;
            float4 v = *(const float4*)&g_H[(size_t)(kb + key) * DD + d4];
            float t0 = __uint_as_float(f2tf32(v.x));
            float t1 = __uint_as_float(f2tf32(v.y));
            float t2 = __uint_as_float(f2tf32(v.z));
            float t3 = __uint_as_float(f2tf32(v.w));
            int kp = perm(key);
            sK[key * STR + perm(d4)    ] = t0;
            sK[key * STR + perm(d4 + 1)] = t1;
            sK[key * STR + perm(d4 + 2)] = t2;
            sK[key * STR + perm(d4 + 3)] = t3;
            sV[(d4    ) * STR + (kp ^ (((d4    ) & 7) << 3))] = t0;
            sV[(d4 + 1) * STR + (kp ^ (((d4 + 1) & 7) << 3))] = t1;
            sV[(d4 + 2) * STR + (kp ^ (((d4 + 2) & 7) << 3))] = t2;
            sV[(d4 + 3) * STR + (kp ^ (((d4 + 3) & 7) << 3))] = t3;
        }
        __syncthreads();

        // ---- S = Q K^T (tensor cores) ----
        float sc[4][4];
#pragma unroll
        for (int na = 0; na < 4; na++)
#pragma unroll
            for (int j = 0; j < 4; j++) sc[na][j] = 0.0f;

#pragma unroll
        for (int ks = 0; ks < 8; ks++) {
#pragma unroll
            for (int na = 0; na < 4; na++) {
                int n = wn * 32 + na * 8 + lr;
                float2 b = *(const float2*)&sK[n * STR + ks * 8 + 2 * lc];
                mma_tf32(sc[na], aQ[ks][0], aQ[ks][1], aQ[ks][2], aQ[ks][3],
                         __float_as_uint(b.x), __float_as_uint(b.y));
            }
        }

        // ---- mask + write masked S to SMEM ----
#pragma unroll
        for (int na = 0; na < 4; na++) {
            int col = wn * 32 + na * 8 + 2 * lc;
            float2 v0, v1;
            v0.x = (am[na][0].x > 0) ? sc[na][0] : NEG_BIG;
            v0.y = (am[na][0].y > 0) ? sc[na][1] : NEG_BIG;
            v1.x = (am[na][1].x > 0) ? sc[na][2] : NEG_BIG;
            v1.y = (am[na][1].y > 0) ? sc[na][3] : NEG_BIG;
            *(float2*)&sSP[lrow0 * STR + col]       = v0;
            *(float2*)&sSP[(lrow0 + 8) * STR + col] = v1;
        }
        __syncthreads();

        // ---- online softmax (SIMT, in place; writes P in A-frag order) ----
        {
            float v[16];
            float tmax = -CUDART_INF_F;
#pragma unroll
            for (int j = 0; j < 16; j++) {
                v[j] = sSP[srow * STR + scol0 + j];
                tmax = fmaxf(tmax, v[j]);
            }
            tmax = fmaxf(tmax, __shfl_xor_sync(0xffffffffu, tmax, 1));
            tmax = fmaxf(tmax, __shfl_xor_sync(0xffffffffu, tmax, 2));
            float mnew  = fmaxf(mrow, tmax);
            float scale = __expf(mrow - mnew);
            mrow = mnew;
            float s = 0.0f;
#pragma unroll
            for (int j = 0; j < 16; j++) {
                v[j] = __expf(v[j] - mnew);
                s += v[j];
            }
            s += __shfl_xor_sync(0xffffffffu, s, 1);
            s += __shfl_xor_sync(0xffffffffu, s, 2);
            lrow = lrow * scale + s;
#pragma unroll
            for (int j = 0; j < 16; j++)
                sSP[srow * STR + scol0 + (j & 8) + perm8(j & 7)] =
                    __uint_as_float(f2tf32(v[j]));
            if ((tid & 3) == 0) sScale[srow] = scale;
        }
        __syncthreads();

        // ---- O rescale + O += P V (tensor cores) ----
        {
            float s0 = sScale[lrow0], s1 = sScale[lrow0 + 8];
#pragma unroll
            for (int na = 0; na < 4; na++) {
                oc[na][0] *= s0; oc[na][1] *= s0;
                oc[na][2] *= s1; oc[na][3] *= s1;
            }
#pragma unroll
            for (int ks = 0; ks < 8; ks++) {
                float2 p0 = *(const float2*)&sSP[lrow0 * STR + ks * 8 + 2 * lc];
                float2 p1 = *(const float2*)&sSP[(lrow0 + 8) * STR + ks * 8 + 2 * lc];
                unsigned a0 = __float_as_uint(p0.x);
                unsigned a1 = __float_as_uint(p1.x);
                unsigned a2 = __float_as_uint(p0.y);
                unsigned a3 = __float_as_uint(p1.y);
#pragma unroll
                for (int na = 0; na < 4; na++) {
                    int n = wn * 32 + na * 8 + lr;   // dim
                    float2 b = *(const float2*)&sV[n * STR + (((ks ^ lr) << 3) + 2 * lc)];
                    mma_tf32(oc[na], a0, a1, a2, a3,
                             __float_as_uint(b.x), __float_as_uint(b.y));
                }
            }
        }
        __syncthreads();
    }

    // ---- epilogue: 1/l, relu, store ----
    if ((tid & 3) == 0) sL[srow] = lrow;
    __syncthreads();
    {
        float inv0 = 1.0f / sL[lrow0];
        float inv1 = 1.0f / sL[lrow0 + 8];
#pragma unroll
        for (int na = 0; na < 4; na++) {
            int col = wn * 32 + na * 8 + 2 * lc;
            float2 o0, o1;
            o0.x = fmaxf(oc[na][0] * inv0, 0.0f);
            o0.y = fmaxf(oc[na][1] * inv0, 0.0f);
            o1.x = fmaxf(oc[na][2] * inv1, 0.0f);
            o1.y = fmaxf(oc[na][3] * inv1, 0.0f);
            *(float2*)&Out[(size_t)grow0 * DD + col]       = o0;
            *(float2*)&Out[(size_t)(grow0 + 8) * DD + col] = o1;
        }
    }
}

// ---------------------------------------------------------------------------
extern "C" void kernel_launch(void* const* d_in, const int* in_sizes, int n_in,
                              void* d_out, int out_size) {
    const float* X = (const float*)d_in[0];
    const int*   A = (const int*)  d_in[1];
    const float* W = (const float*)d_in[2];
    const float* b = (const float*)d_in[3];
    float* Out = (float*)d_out;

    const int smem_bytes = (3 * 64 * STR + 128) * (int)sizeof(float);  // 52736 B
    static bool attr_set = false;
    if (!attr_set) {
        cudaFuncSetAttribute(flash_mma,
                             cudaFuncAttributeMaxDynamicSharedMemorySize,
                             smem_bytes);
        attr_set = true;
    }

    h_kernel<<<NN / 4, NT>>>(X, W, b);
    flash_mma<<<NN / BM, NT, smem_bytes>>>(A, Out);
}

// round 3
// speedup vs baseline: 2.0066x; 1.2464x over previous
#include <cuda_runtime.h>
#include <math_constants.h>

#define NN       8192
#define IN_DIM   200
#define DD       64
#define BM       64
#define BN       64
#define NT       128
#define STR      68
#define PSTR     68
#define SPLITS   3
#define NEG_BIG  (-1.0e9f)

// Scratch
__device__ float g_H[NN * DD];                       // 2 MB
__device__ float g_Op[SPLITS * NN * DD];             // 6 MB partial O (unnormalized)
__device__ float g_mp[SPLITS * NN];
__device__ float g_lp[SPLITS * NN];

// ---------------------------------------------------------------------------
__device__ __forceinline__ unsigned f2tf32(float f) {
    unsigned r;
    asm("cvt.rna.tf32.f32 %0, %1;" : "=r"(r) : "f"(f));
    return r;
}
__device__ __forceinline__ int perm8(int j) { return ((j & 3) << 1) | (j >> 2); }
__device__ __forceinline__ int perm (int j) { return (j & ~7) | perm8(j & 7); }

__device__ __forceinline__ void mma_tf32(float c[4],
                                         unsigned a0, unsigned a1,
                                         unsigned a2, unsigned a3,
                                         unsigned b0, unsigned b1) {
    asm volatile(
        "mma.sync.aligned.m16n8k8.row.col.f32.tf32.tf32.f32 "
        "{%0,%1,%2,%3}, {%4,%5,%6,%7}, {%8,%9}, {%0,%1,%2,%3};"
        : "+f"(c[0]), "+f"(c[1]), "+f"(c[2]), "+f"(c[3])
        : "r"(a0), "r"(a1), "r"(a2), "r"(a3), "r"(b0), "r"(b1));
}

// ---------------------------------------------------------------------------
// Kernel 1: H = X @ W + b.  X rows staged through smem (no L1 broadcast storm).
// ---------------------------------------------------------------------------
__global__ void h_kernel(const float* __restrict__ X,
                         const float* __restrict__ W,
                         const float* __restrict__ b) {
    __shared__ float sx[4 * IN_DIM];
    const int tid  = threadIdx.x;
    const int rowq = blockIdx.x * 4;
    for (int i = tid; i < 4 * IN_DIM; i += 256)
        sx[i] = X[(size_t)rowq * IN_DIM + i];
    __syncthreads();
    const int r = tid >> 6, d = tid & 63;
    const float* x = sx + r * IN_DIM;
    float acc = b[d];
#pragma unroll 8
    for (int k = 0; k < IN_DIM; k++)
        acc = fmaf(x[k], W[k * DD + d], acc);
    g_H[(rowq + r) * DD + d] = acc;
}

// ---------------------------------------------------------------------------
// Kernel 2: split-K flash attention. grid = SPLITS*128 CTAs, 128 thr, 3 CTA/SM.
// Warp w owns rows [w*16, w*16+16) x all 64 keys -> in-register softmax.
// ---------------------------------------------------------------------------
__global__ __launch_bounds__(NT, 3)
void flash_mma(const int* __restrict__ A) {
    extern __shared__ float sm[];
    float*    sK  = sm;                       // [64][STR] B-frags for S
    float*    sV  = sK + BN * STR;            // [64][STR] B-frags for O
    float*    sP  = sV + DD * STR;            // per-warp [16][PSTR]
    unsigned* sAb = (unsigned*)(sP + 4 * 16 * PSTR);  // [2][64][2] bitmasks

    const int tid   = threadIdx.x;
    const int lane  = tid & 31;
    const int w     = tid >> 5;
    const int lr    = lane >> 2;
    const int lc    = lane & 3;
    const int split = blockIdx.x >> 7;        // 0..2
    const int qt    = blockIdx.x & 127;
    const int qbase = qt * BM;
    const int t0    = 43 * split;
    const int t1    = (split == 2) ? 128 : 43 * (split + 1);

    const int r0 = qbase + w * 16 + lr;       // first of this thread's two rows

    // ---- Q fragments in registers ----
    unsigned aQ[8][4];
#pragma unroll
    for (int ks = 0; ks < 8; ks++) {
        int c0 = ks * 8 + lc;
        aQ[ks][0] = f2tf32(g_H[(size_t)r0 * DD + c0]);
        aQ[ks][1] = f2tf32(g_H[(size_t)(r0 + 8) * DD + c0]);
        aQ[ks][2] = f2tf32(g_H[(size_t)r0 * DD + c0 + 4]);
        aQ[ks][3] = f2tf32(g_H[(size_t)(r0 + 8) * DD + c0 + 4]);
    }

    float oc[8][4];
#pragma unroll
    for (int na = 0; na < 8; na++)
#pragma unroll
        for (int j = 0; j < 4; j++) oc[na][j] = 0.0f;

    float m0 = -CUDART_INF_F, m1 = -CUDART_INF_F, l0 = 0.0f, l1 = 0.0f;

    // ---- A bitmask pack: thread i -> row i>>1, 32-key half i&1 ----
    const int arow  = tid >> 1;
    const int ahalf = tid & 1;
    const int4* abase = (const int4*)(A + (size_t)(qbase + arow) * NN + ahalf * 32);

    {   // prefetch tile t0 into buf 0
        const int4* p = abase + t0 * (BN / 4);
        unsigned bbits = 0;
#pragma unroll
        for (int j = 0; j < 8; j++) {
            int4 v = p[j];
            bbits |= (v.x > 0 ? 1u << (4 * j)     : 0u)
                   | (v.y > 0 ? 1u << (4 * j + 1) : 0u)
                   | (v.z > 0 ? 1u << (4 * j + 2) : 0u)
                   | (v.w > 0 ? 1u << (4 * j + 3) : 0u);
        }
        sAb[arow * 2 + ahalf] = bbits;
    }

    for (int t = t0; t < t1; t++) {
        const int buf = (t - t0) & 1;
        __syncthreads();   // prior tile's reads of sK/sV/sAb complete

        // ---- stage K/V tile t (tf32, two layouts) ----
#pragma unroll
        for (int ii = 0; ii < 8; ii++) {
            int i   = tid + ii * NT;
            int key = i >> 4;
            int d4  = (i & 15) * 4;
            float4 v = *(const float4*)&g_H[(size_t)(t * BN + key) * DD + d4];
            float tt0 = __uint_as_float(f2tf32(v.x));
            float tt1 = __uint_as_float(f2tf32(v.y));
            float tt2 = __uint_as_float(f2tf32(v.z));
            float tt3 = __uint_as_float(f2tf32(v.w));
            int kp = perm(key);
            sK[key * STR + perm(d4)    ] = tt0;
            sK[key * STR + perm(d4 + 1)] = tt1;
            sK[key * STR + perm(d4 + 2)] = tt2;
            sK[key * STR + perm(d4 + 3)] = tt3;
            sV[(d4    ) * STR + (kp ^ (((d4    ) & 7) << 3))] = tt0;
            sV[(d4 + 1) * STR + (kp ^ (((d4 + 1) & 7) << 3))] = tt1;
            sV[(d4 + 2) * STR + (kp ^ (((d4 + 2) & 7) << 3))] = tt2;
            sV[(d4 + 3) * STR + (kp ^ (((d4 + 3) & 7) << 3))] = tt3;
        }
        // ---- prefetch+pack A for tile t+1 (hides DRAM latency behind mma) ----
        if (t + 1 < t1) {
            const int4* p = abase + (t + 1) * (BN / 4);
            unsigned bbits = 0;
#pragma unroll
            for (int j = 0; j < 8; j++) {
                int4 v = p[j];
                bbits |= (v.x > 0 ? 1u << (4 * j)     : 0u)
                       | (v.y > 0 ? 1u << (4 * j + 1) : 0u)
                       | (v.z > 0 ? 1u << (4 * j + 2) : 0u)
                       | (v.w > 0 ? 1u << (4 * j + 3) : 0u);
            }
            sAb[(buf ^ 1) * 128 + arow * 2 + ahalf] = bbits;
        }
        __syncthreads();   // sK/sV published; sAb[buf^1] published

        // ---- S = Q K^T ----
        float sc[8][4];
#pragma unroll
        for (int na = 0; na < 8; na++)
#pragma unroll
            for (int j = 0; j < 4; j++) sc[na][j] = 0.0f;
#pragma unroll
        for (int ks = 0; ks < 8; ks++) {
#pragma unroll
            for (int na = 0; na < 8; na++) {
                float2 bf = *(const float2*)&sK[(na * 8 + lr) * STR + ks * 8 + 2 * lc];
                mma_tf32(sc[na], aQ[ks][0], aQ[ks][1], aQ[ks][2], aQ[ks][3],
                         __float_as_uint(bf.x), __float_as_uint(bf.y));
            }
        }

        // ---- mask from bitmask words ----
        {
            unsigned r0w0 = sAb[buf * 128 + (w * 16 + lr) * 2];
            unsigned r0w1 = sAb[buf * 128 + (w * 16 + lr) * 2 + 1];
            unsigned r1w0 = sAb[buf * 128 + (w * 16 + lr + 8) * 2];
            unsigned r1w1 = sAb[buf * 128 + (w * 16 + lr + 8) * 2 + 1];
#pragma unroll
            for (int na = 0; na < 8; na++) {
                unsigned wa0 = (na < 4) ? r0w0 : r0w1;
                unsigned wa1 = (na < 4) ? r1w0 : r1w1;
                int sh = (na * 8 + 2 * lc) & 31;
                sc[na][0] = ((wa0 >> sh)       & 1) ? sc[na][0] : NEG_BIG;
                sc[na][1] = ((wa0 >> (sh + 1)) & 1) ? sc[na][1] : NEG_BIG;
                sc[na][2] = ((wa1 >> sh)       & 1) ? sc[na][2] : NEG_BIG;
                sc[na][3] = ((wa1 >> (sh + 1)) & 1) ? sc[na][3] : NEG_BIG;
            }
        }

        // ---- in-register online softmax ----
        float mt0 = -CUDART_INF_F, mt1 = -CUDART_INF_F;
#pragma unroll
        for (int na = 0; na < 8; na++) {
            mt0 = fmaxf(mt0, fmaxf(sc[na][0], sc[na][1]));
            mt1 = fmaxf(mt1, fmaxf(sc[na][2], sc[na][3]));
        }
        mt0 = fmaxf(mt0, __shfl_xor_sync(0xffffffffu, mt0, 1));
        mt0 = fmaxf(mt0, __shfl_xor_sync(0xffffffffu, mt0, 2));
        mt1 = fmaxf(mt1, __shfl_xor_sync(0xffffffffu, mt1, 1));
        mt1 = fmaxf(mt1, __shfl_xor_sync(0xffffffffu, mt1, 2));

        float mn0 = fmaxf(m0, mt0), mn1 = fmaxf(m1, mt1);
        float scl0 = __expf(m0 - mn0), scl1 = __expf(m1 - mn1);
        m0 = mn0; m1 = mn1;

        float s0 = 0.0f, s1 = 0.0f;
#pragma unroll
        for (int na = 0; na < 8; na++) {
            sc[na][0] = __expf(sc[na][0] - m0);
            sc[na][1] = __expf(sc[na][1] - m0);
            sc[na][2] = __expf(sc[na][2] - m1);
            sc[na][3] = __expf(sc[na][3] - m1);
            s0 += sc[na][0] + sc[na][1];
            s1 += sc[na][2] + sc[na][3];
        }
        s0 += __shfl_xor_sync(0xffffffffu, s0, 1);
        s0 += __shfl_xor_sync(0xffffffffu, s0, 2);
        s1 += __shfl_xor_sync(0xffffffffu, s1, 1);
        s1 += __shfl_xor_sync(0xffffffffu, s1, 2);
        l0 = l0 * scl0 + s0;
        l1 = l1 * scl1 + s1;

#pragma unroll
        for (int na = 0; na < 8; na++) {
            oc[na][0] *= scl0; oc[na][1] *= scl0;
            oc[na][2] *= scl1; oc[na][3] *= scl1;
        }

        // ---- P (tf32) to warp-private smem in A-frag perm ----
        float* pw = sP + w * 16 * PSTR;
#pragma unroll
        for (int na = 0; na < 8; na++) {
            pw[lr * PSTR       + na * 8 + perm8(2 * lc)]     = __uint_as_float(f2tf32(sc[na][0]));
            pw[lr * PSTR       + na * 8 + perm8(2 * lc + 1)] = __uint_as_float(f2tf32(sc[na][1]));
            pw[(lr + 8) * PSTR + na * 8 + perm8(2 * lc)]     = __uint_as_float(f2tf32(sc[na][2]));
            pw[(lr + 8) * PSTR + na * 8 + perm8(2 * lc + 1)] = __uint_as_float(f2tf32(sc[na][3]));
        }
        __syncwarp();

        // ---- O += P V ----
#pragma unroll
        for (int ks = 0; ks < 8; ks++) {
            float2 pa = *(const float2*)&pw[lr * PSTR + ks * 8 + 2 * lc];
            float2 pb = *(const float2*)&pw[(lr + 8) * PSTR + ks * 8 + 2 * lc];
            unsigned a0 = __float_as_uint(pa.x);
            unsigned a1 = __float_as_uint(pb.x);
            unsigned a2 = __float_as_uint(pa.y);
            unsigned a3 = __float_as_uint(pb.y);
#pragma unroll
            for (int na = 0; na < 8; na++) {
                float2 bf = *(const float2*)&sV[(na * 8 + lr) * STR + (((ks ^ lr) << 3) + 2 * lc)];
                mma_tf32(oc[na], a0, a1, a2, a3,
                         __float_as_uint(bf.x), __float_as_uint(bf.y));
            }
        }
    }

    // ---- write partials ----
    float* Op = g_Op + (size_t)split * NN * DD;
#pragma unroll
    for (int na = 0; na < 8; na++) {
        int c0 = na * 8 + 2 * lc;
        *(float2*)&Op[(size_t)r0 * DD + c0]       = make_float2(oc[na][0], oc[na][1]);
        *(float2*)&Op[(size_t)(r0 + 8) * DD + c0] = make_float2(oc[na][2], oc[na][3]);
    }
    if (lc == 0) {
        g_mp[split * NN + r0]     = m0;
        g_mp[split * NN + r0 + 8] = m1;
        g_lp[split * NN + r0]     = l0;
        g_lp[split * NN + r0 + 8] = l1;
    }
}

// ---------------------------------------------------------------------------
// Kernel 3: merge the 3 split partials, normalize, relu.
// ---------------------------------------------------------------------------
__global__ void merge_kernel(float* __restrict__ Out) {
    int idx = blockIdx.x * 256 + threadIdx.x;      // over NN*DD
    int row = idx >> 6;
    float a = g_mp[row], bm = g_mp[NN + row], c = g_mp[2 * NN + row];
    float M = fmaxf(a, fmaxf(bm, c));
    float w0 = __expf(a - M), w1 = __expf(bm - M), w2 = __expf(c - M);
    float denom = w0 * g_lp[row] + w1 * g_lp[NN + row] + w2 * g_lp[2 * NN + row];
    float num = w0 * g_Op[idx] + w1 * g_Op[NN * DD + idx] + w2 * g_Op[2 * NN * DD + idx];
    Out[idx] = fmaxf(num / denom, 0.0f);
}

// ---------------------------------------------------------------------------
extern "C" void kernel_launch(void* const* d_in, const int* in_sizes, int n_in,
                              void* d_out, int out_size) {
    const float* X = (const float*)d_in[0];
    const int*   A = (const int*)  d_in[1];
    const float* W = (const float*)d_in[2];
    const float* b = (const float*)d_in[3];
    float* Out = (float*)d_out;

    const int smem_bytes = (2 * BN * STR + 4 * 16 * PSTR) * 4 + 2 * 64 * 2 * 4; // 53248
    static bool attr_set = false;
    if (!attr_set) {
        cudaFuncSetAttribute(flash_mma,
                             cudaFuncAttributeMaxDynamicSharedMemorySize,
                             smem_bytes);
        attr_set = true;
    }

    h_kernel<<<NN / 4, 256>>>(X, W, b);
    flash_mma<<<SPLITS * 128, NT, smem_bytes>>>(A);
    merge_kernel<<<NN * DD / 256, 256>>>(Out);
}

// round 6
// speedup vs baseline: 2.1468x; 1.0698x over previous
#include <cuda_runtime.h>
#include <math_constants.h>

#define NN       8192
#define IN_DIM   200
#define DD       64
#define BM       64
#define BN       64
#define NT       128
#define STR      68
#define SPLITS   4
#define NEG_BIG  (-1.0e9f)

// Scratch
__device__ float g_H[NN * DD];                 // 2 MB
__device__ float g_Op[SPLITS * NN * DD];       // 8 MB unnormalized partial O
__device__ float g_mp[SPLITS * NN];            // partial row maxes
__device__ float g_lp[SPLITS * NN];            // partial sums

// ---------------------------------------------------------------------------
__device__ __forceinline__ unsigned f2tf32(float f) {
    unsigned r;
    asm("cvt.rna.tf32.f32 %0, %1;" : "=r"(r) : "f"(f));
    return r;
}
__device__ __forceinline__ int perm8(int j) { return ((j & 3) << 1) | (j >> 2); }
__device__ __forceinline__ int perm (int j) { return (j & ~7) | perm8(j & 7); }

__device__ __forceinline__ void mma_tf32(float c[4],
                                         unsigned a0, unsigned a1,
                                         unsigned a2, unsigned a3,
                                         unsigned b0, unsigned b1) {
    asm volatile(
        "mma.sync.aligned.m16n8k8.row.col.f32.tf32.tf32.f32 "
        "{%0,%1,%2,%3}, {%4,%5,%6,%7}, {%8,%9}, {%0,%1,%2,%3};"
        : "+f"(c[0]), "+f"(c[1]), "+f"(c[2]), "+f"(c[3])
        : "r"(a0), "r"(a1), "r"(a2), "r"(a3), "r"(b0), "r"(b1));
}

// ---------------------------------------------------------------------------
// Kernel 1: H = X @ W + b.  8 rows/block, 2 rows/thread (2 FMA chains, W reuse).
// ---------------------------------------------------------------------------
__global__ void h_kernel(const float* __restrict__ X,
                         const float* __restrict__ W,
                         const float* __restrict__ b) {
    __shared__ float sx[8 * IN_DIM];
    const int tid  = threadIdx.x;
    const int rowq = blockIdx.x * 8;
    for (int i = tid; i < 8 * IN_DIM; i += 256)
        sx[i] = X[(size_t)rowq * IN_DIM + i];
    __syncthreads();
    const int r = tid >> 6, d = tid & 63;
    const float* x0 = sx + r * IN_DIM;
    const float* x1 = sx + (r + 4) * IN_DIM;
    float acc0 = b[d], acc1 = acc0;
#pragma unroll 8
    for (int k = 0; k < IN_DIM; k++) {
        float wv = W[k * DD + d];
        acc0 = fmaf(x0[k], wv, acc0);
        acc1 = fmaf(x1[k], wv, acc1);
    }
    g_H[(rowq + r) * DD + d]     = acc0;
    g_H[(rowq + r + 4) * DD + d] = acc1;
}

// ---------------------------------------------------------------------------
// Kernel 2: split-K flash attention with online softmax.
// grid = SPLITS*128, 128 thr, 4 CTAs/SM. Warp w owns rows [w*16,w*16+16).
// K stored row-permuted so S C-frags ARE the O A-frags (no P smem roundtrip).
// ---------------------------------------------------------------------------
__global__ __launch_bounds__(NT, 4)
void flash_mma(const int* __restrict__ A) {
    extern __shared__ float sm[];
    float*    sK  = sm;                       // [64][STR] B-frags for S (row-perm keys)
    float*    sV  = sK + BN * STR;            // [64][STR] B-frags for O (xor-swizzled)
    unsigned* sAb = (unsigned*)(sV + DD * STR);  // [2][64][2] adjacency bitmasks

    const int tid   = threadIdx.x;
    const int lane  = tid & 31;
    const int w     = tid >> 5;
    const int lr    = lane >> 2;
    const int lc    = lane & 3;
    const int split = blockIdx.x >> 7;        // 0..3
    const int qt    = blockIdx.x & 127;
    const int qbase = qt * BM;
    const int t0    = split * 32;
    const int t1    = t0 + 32;

    const int r0 = qbase + w * 16 + lr;

    // ---- Q fragments in registers ----
    unsigned aQ[8][4];
#pragma unroll
    for (int ks = 0; ks < 8; ks++) {
        int c0 = ks * 8 + lc;
        aQ[ks][0] = f2tf32(g_H[(size_t)r0 * DD + c0]);
        aQ[ks][1] = f2tf32(g_H[(size_t)(r0 + 8) * DD + c0]);
        aQ[ks][2] = f2tf32(g_H[(size_t)r0 * DD + c0 + 4]);
        aQ[ks][3] = f2tf32(g_H[(size_t)(r0 + 8) * DD + c0 + 4]);
    }

    float oc[8][4];
#pragma unroll
    for (int na = 0; na < 8; na++)
#pragma unroll
        for (int j = 0; j < 4; j++) oc[na][j] = 0.0f;

    float m0 = -CUDART_INF_F, m1 = -CUDART_INF_F;
    float l0 = 0.0f, l1 = 0.0f;

    // ---- A bitmask pack: thread i -> row i>>1, 32-key half i&1 ----
    const int arow  = tid >> 1;
    const int ahalf = tid & 1;
    const int4* abase = (const int4*)(A + (size_t)(qbase + arow) * NN + ahalf * 32);

    {   // prefetch tile t0 into buf 0
        const int4* p = abase + t0 * (BN / 4);
        unsigned bbits = 0;
#pragma unroll
        for (int j = 0; j < 8; j++) {
            int4 v = p[j];
            bbits |= (v.x > 0 ? 1u << (4 * j)     : 0u)
                   | (v.y > 0 ? 1u << (4 * j + 1) : 0u)
                   | (v.z > 0 ? 1u << (4 * j + 2) : 0u)
                   | (v.w > 0 ? 1u << (4 * j + 3) : 0u);
        }
        sAb[arow * 2 + ahalf] = bbits;
    }

    for (int t = t0; t < t1; t++) {
        const int buf = (t - t0) & 1;
        __syncthreads();   // prior tile's reads of sK/sV/sAb complete

        // ---- stage K/V tile t (tf32, two layouts) ----
#pragma unroll
        for (int ii = 0; ii < 8; ii++) {
            int i   = tid + ii * NT;
            int key = i >> 4;
            int d4  = (i & 15) * 4;
            float4 v = *(const float4*)&g_H[(size_t)(t * BN + key) * DD + d4];
            float tt0 = __uint_as_float(f2tf32(v.x));
            float tt1 = __uint_as_float(f2tf32(v.y));
            float tt2 = __uint_as_float(f2tf32(v.z));
            float tt3 = __uint_as_float(f2tf32(v.w));
            int kp   = perm(key);                       // for sV (k-dim perm)
            int krow = (key & ~7) | perm8(key & 7);     // for sK (n-dim perm)
            sK[krow * STR + perm(d4)    ] = tt0;
            sK[krow * STR + perm(d4 + 1)] = tt1;
            sK[krow * STR + perm(d4 + 2)] = tt2;
            sK[krow * STR + perm(d4 + 3)] = tt3;
            sV[(d4    ) * STR + (kp ^ (((d4    ) & 7) << 3))] = tt0;
            sV[(d4 + 1) * STR + (kp ^ (((d4 + 1) & 7) << 3))] = tt1;
            sV[(d4 + 2) * STR + (kp ^ (((d4 + 2) & 7) << 3))] = tt2;
            sV[(d4 + 3) * STR + (kp ^ (((d4 + 3) & 7) << 3))] = tt3;
        }
        // ---- prefetch+pack A for tile t+1 (hidden behind mma work) ----
        if (t + 1 < t1) {
            const int4* p = abase + (t + 1) * (BN / 4);
            unsigned bbits = 0;
#pragma unroll
            for (int j = 0; j < 8; j++) {
                int4 v = p[j];
                bbits |= (v.x > 0 ? 1u << (4 * j)     : 0u)
                       | (v.y > 0 ? 1u << (4 * j + 1) : 0u)
                       | (v.z > 0 ? 1u << (4 * j + 2) : 0u)
                       | (v.w > 0 ? 1u << (4 * j + 3) : 0u);
            }
            sAb[(buf ^ 1) * 128 + arow * 2 + ahalf] = bbits;
        }
        __syncthreads();   // sK/sV published; sAb[buf^1] published

        // ---- S = Q K^T ----
        float sc[8][4];
#pragma unroll
        for (int na = 0; na < 8; na++)
#pragma unroll
            for (int j = 0; j < 4; j++) sc[na][j] = 0.0f;
#pragma unroll
        for (int ks = 0; ks < 8; ks++) {
#pragma unroll
            for (int na = 0; na < 8; na++) {
                float2 bf = *(const float2*)&sK[(na * 8 + lr) * STR + ks * 8 + 2 * lc];
                mma_tf32(sc[na], aQ[ks][0], aQ[ks][1], aQ[ks][2], aQ[ks][3],
                         __float_as_uint(bf.x), __float_as_uint(bf.y));
            }
        }

        // ---- mask to NEG_BIG ----
        // sc[na][0]=(lr, k=na*8+lc)  sc[na][1]=(lr, k+4)
        // sc[na][2]=(lr+8, k)        sc[na][3]=(lr+8, k+4)
        {
            unsigned b0w0 = sAb[buf * 128 + (w * 16 + lr) * 2];
            unsigned b0w1 = sAb[buf * 128 + (w * 16 + lr) * 2 + 1];
            unsigned b1w0 = sAb[buf * 128 + (w * 16 + lr + 8) * 2];
            unsigned b1w1 = sAb[buf * 128 + (w * 16 + lr + 8) * 2 + 1];
#pragma unroll
            for (int na = 0; na < 8; na++) {
                unsigned m0w = (na < 4) ? b0w0 : b0w1;
                unsigned m1w = (na < 4) ? b1w0 : b1w1;
                int sh = ((na & 3) << 3) + lc;
                sc[na][0] = ((m0w >> sh)       & 1) ? sc[na][0] : NEG_BIG;
                sc[na][1] = ((m0w >> (sh + 4)) & 1) ? sc[na][1] : NEG_BIG;
                sc[na][2] = ((m1w >> sh)       & 1) ? sc[na][2] : NEG_BIG;
                sc[na][3] = ((m1w >> (sh + 4)) & 1) ? sc[na][3] : NEG_BIG;
            }
        }

        // ---- online softmax; sc becomes the P A-fragments in place ----
        {
            float mt0 = NEG_BIG, mt1 = NEG_BIG;
#pragma unroll
            for (int na = 0; na < 8; na++) {
                mt0 = fmaxf(mt0, fmaxf(sc[na][0], sc[na][1]));
                mt1 = fmaxf(mt1, fmaxf(sc[na][2], sc[na][3]));
            }
            mt0 = fmaxf(mt0, __shfl_xor_sync(0xffffffffu, mt0, 1));
            mt0 = fmaxf(mt0, __shfl_xor_sync(0xffffffffu, mt0, 2));
            mt1 = fmaxf(mt1, __shfl_xor_sync(0xffffffffu, mt1, 1));
            mt1 = fmaxf(mt1, __shfl_xor_sync(0xffffffffu, mt1, 2));

            float mn0 = fmaxf(m0, mt0), mn1 = fmaxf(m1, mt1);
            float scl0 = __expf(m0 - mn0), scl1 = __expf(m1 - mn1);
            m0 = mn0; m1 = mn1;

            float s0 = 0.0f, s1 = 0.0f;
#pragma unroll
            for (int na = 0; na < 8; na++) {
                float p00 = __expf(sc[na][0] - m0);
                float p01 = __expf(sc[na][1] - m0);
                float p10 = __expf(sc[na][2] - m1);
                float p11 = __expf(sc[na][3] - m1);
                s0 += p00 + p01;
                s1 += p10 + p11;
                sc[na][0] = __uint_as_float(f2tf32(p00));
                sc[na][1] = __uint_as_float(f2tf32(p01));
                sc[na][2] = __uint_as_float(f2tf32(p10));
                sc[na][3] = __uint_as_float(f2tf32(p11));
            }
            s0 += __shfl_xor_sync(0xffffffffu, s0, 1);
            s0 += __shfl_xor_sync(0xffffffffu, s0, 2);
            s1 += __shfl_xor_sync(0xffffffffu, s1, 1);
            s1 += __shfl_xor_sync(0xffffffffu, s1, 2);
            l0 = l0 * scl0 + s0;
            l1 = l1 * scl1 + s1;

#pragma unroll
            for (int na = 0; na < 8; na++) {
                oc[na][0] *= scl0; oc[na][1] *= scl0;
                oc[na][2] *= scl1; oc[na][3] *= scl1;
            }
        }

        // ---- O += P V (P direct from registers) ----
#pragma unroll
        for (int ks = 0; ks < 8; ks++) {
            unsigned a0 = __float_as_uint(sc[ks][0]);   // (lr,   k)
            unsigned a1 = __float_as_uint(sc[ks][2]);   // (lr+8, k)
            unsigned a2 = __float_as_uint(sc[ks][1]);   // (lr,   k+4)
            unsigned a3 = __float_as_uint(sc[ks][3]);   // (lr+8, k+4)
#pragma unroll
            for (int na = 0; na < 8; na++) {
                float2 bf = *(const float2*)&sV[(na * 8 + lr) * STR + (((ks ^ lr) << 3) + 2 * lc)];
                mma_tf32(oc[na], a0, a1, a2, a3,
                         __float_as_uint(bf.x), __float_as_uint(bf.y));
            }
        }
    }

    // ---- write partials ----
    float* Op = g_Op + (size_t)split * NN * DD;
#pragma unroll
    for (int na = 0; na < 8; na++) {
        int c0 = na * 8 + 2 * lc;
        *(float2*)&Op[(size_t)r0 * DD + c0]       = make_float2(oc[na][0], oc[na][1]);
        *(float2*)&Op[(size_t)(r0 + 8) * DD + c0] = make_float2(oc[na][2], oc[na][3]);
    }
    if (lc == 0) {
        g_mp[split * NN + r0]     = m0;
        g_mp[split * NN + r0 + 8] = m1;
        g_lp[split * NN + r0]     = l0;
        g_lp[split * NN + r0 + 8] = l1;
    }
}

// ---------------------------------------------------------------------------
// Kernel 3: m-aware merge of the 4 split partials, normalize, relu.
// ---------------------------------------------------------------------------
__global__ void merge_kernel(float* __restrict__ Out) {
    int idx = blockIdx.x * 256 + threadIdx.x;      // over NN*DD
    int row = idx >> 6;
    float ma = g_mp[row], mb = g_mp[NN + row];
    float mc = g_mp[2 * NN + row], md = g_mp[3 * NN + row];
    float M = fmaxf(fmaxf(ma, mb), fmaxf(mc, md));
    float w0 = __expf(ma - M), w1 = __expf(mb - M);
    float w2 = __expf(mc - M), w3 = __expf(md - M);
    float denom = w0 * g_lp[row] + w1 * g_lp[NN + row]
                + w2 * g_lp[2 * NN + row] + w3 * g_lp[3 * NN + row];
    float num = w0 * g_Op[idx] + w1 * g_Op[NN * DD + idx]
              + w2 * g_Op[2 * NN * DD + idx] + w3 * g_Op[3 * NN * DD + idx];
    Out[idx] = fmaxf(num / denom, 0.0f);
}

// ---------------------------------------------------------------------------
extern "C" void kernel_launch(void* const* d_in, const int* in_sizes, int n_in,
                              void* d_out, int out_size) {
    const float* X = (const float*)d_in[0];
    const int*   A = (const int*)  d_in[1];
    const float* W = (const float*)d_in[2];
    const float* b = (const float*)d_in[3];
    float* Out = (float*)d_out;

    const int smem_bytes = 2 * BN * STR * 4 + 2 * 64 * 2 * 4;   // 35840 B
    static bool attr_set = false;
    if (!attr_set) {
        cudaFuncSetAttribute(flash_mma,
                             cudaFuncAttributeMaxDynamicSharedMemorySize,
                             smem_bytes);
        attr_set = true;
    }

    h_kernel<<<NN / 8, 256>>>(X, W, b);
    flash_mma<<<SPLITS * 128, NT, smem_bytes>>>(A);
    merge_kernel<<<NN * DD / 256, 256>>>(Out);
}

// round 7
// speedup vs baseline: 2.6737x; 1.2454x over previous
#include <cuda_runtime.h>
#include <math_constants.h>

#define NN       8192
#define IN_DIM   200
#define DD       64
#define BM       128
#define BN       64
#define NT       256
#define STRK     72          // sK / sQ stride (floats): conflict-free frag loads
#define STRV     68          // sV stride (floats): conflict-free with xor swizzle
#define SPLITS   4
#define NEG_BIG  (-1.0e9f)

// Scratch
__device__ float g_H[NN * DD];                 // 2 MB
__device__ float g_Op[SPLITS * NN * DD];       // 8 MB unnormalized partial O
__device__ float g_mp[SPLITS * NN];            // partial row maxes
__device__ float g_lp[SPLITS * NN];            // partial sums

// ---------------------------------------------------------------------------
__device__ __forceinline__ unsigned f2tf32(float f) {
    unsigned r;
    asm("cvt.rna.tf32.f32 %0, %1;" : "=r"(r) : "f"(f));
    return r;
}
__device__ __forceinline__ int perm8(int j) { return ((j & 3) << 1) | (j >> 2); }
__device__ __forceinline__ int perm (int j) { return (j & ~7) | perm8(j & 7); }

__device__ __forceinline__ void mma_tf32(float c[4],
                                         unsigned a0, unsigned a1,
                                         unsigned a2, unsigned a3,
                                         unsigned b0, unsigned b1) {
    asm volatile(
        "mma.sync.aligned.m16n8k8.row.col.f32.tf32.tf32.f32 "
        "{%0,%1,%2,%3}, {%4,%5,%6,%7}, {%8,%9}, {%0,%1,%2,%3};"
        : "+f"(c[0]), "+f"(c[1]), "+f"(c[2]), "+f"(c[3])
        : "r"(a0), "r"(a1), "r"(a2), "r"(a3), "r"(b0), "r"(b1));
}

// ---------------------------------------------------------------------------
// Kernel 1: H = X @ W + b.
// ---------------------------------------------------------------------------
__global__ void h_kernel(const float* __restrict__ X,
                         const float* __restrict__ W,
                         const float* __restrict__ b) {
    __shared__ float sx[8 * IN_DIM];
    const int tid  = threadIdx.x;
    const int rowq = blockIdx.x * 8;
    for (int i = tid; i < 8 * IN_DIM; i += 256)
        sx[i] = X[(size_t)rowq * IN_DIM + i];
    __syncthreads();
    const int r = tid >> 6, d = tid & 63;
    const float* x0 = sx + r * IN_DIM;
    const float* x1 = sx + (r + 4) * IN_DIM;
    float acc0 = b[d], acc1 = acc0;
#pragma unroll 8
    for (int k = 0; k < IN_DIM; k++) {
        float wv = W[k * DD + d];
        acc0 = fmaf(x0[k], wv, acc0);
        acc1 = fmaf(x1[k], wv, acc1);
    }
    g_H[(rowq + r) * DD + d]     = acc0;
    g_H[(rowq + r + 4) * DD + d] = acc1;
}

// ---------------------------------------------------------------------------
// Kernel 2: split-K flash attention, online softmax, BM=128 (8 warps share
// one K/V tile -> half the redundant fragment traffic). Q in smem (no spills).
// ---------------------------------------------------------------------------
__global__ __launch_bounds__(NT, 2)
void flash_mma(const int* __restrict__ A) {
    extern __shared__ float sm[];
    float*    sQ  = sm;                       // [128][STRK] A-frag layout
    float*    sK  = sQ + BM * STRK;           // [64][STRK]  B-frags for S (row-perm)
    float*    sV  = sK + BN * STRK;           // [64][STRV]  B-frags for O (xor swz)
    unsigned* sAb = (unsigned*)(sV + DD * STRV);  // [2][128][2] adjacency bitmasks

    const int tid   = threadIdx.x;
    const int lane  = tid & 31;
    const int w     = tid >> 5;               // 0..7
    const int lr    = lane >> 2;              // 0..7
    const int lc    = lane & 3;               // 0..3
    const int split = blockIdx.x >> 6;        // 0..3
    const int qt    = blockIdx.x & 63;
    const int qbase = qt * BM;
    const int t0    = split * 32;
    const int t1    = t0 + 32;

    const int lrow0 = w * 16 + lr;            // CTA-local row
    const int r0    = qbase + lrow0;

    // ---- stage Q tile into smem (fragment layout, tf32) ----
#pragma unroll
    for (int ii = 0; ii < 8; ii++) {
        int i   = tid + ii * NT;              // float4 index over 128x64
        int row = i >> 4;
        int d4  = (i & 15) * 4;
        float4 v = *(const float4*)&g_H[(size_t)(qbase + row) * DD + d4];
        sQ[row * STRK + perm(d4)    ] = __uint_as_float(f2tf32(v.x));
        sQ[row * STRK + perm(d4 + 1)] = __uint_as_float(f2tf32(v.y));
        sQ[row * STRK + perm(d4 + 2)] = __uint_as_float(f2tf32(v.z));
        sQ[row * STRK + perm(d4 + 3)] = __uint_as_float(f2tf32(v.w));
    }

    float oc[8][4];
#pragma unroll
    for (int na = 0; na < 8; na++)
#pragma unroll
        for (int j = 0; j < 4; j++) oc[na][j] = 0.0f;

    float m0 = -CUDART_INF_F, m1 = -CUDART_INF_F;
    float l0 = 0.0f, l1 = 0.0f;

    // ---- A bitmask pack: thread i -> row i>>1, 32-key half i&1 ----
    const int arow  = tid >> 1;               // 0..127
    const int ahalf = tid & 1;
    const int4* abase = (const int4*)(A + (size_t)(qbase + arow) * NN + ahalf * 32);

    {   // prefetch tile t0 into buf 0
        const int4* p = abase + t0 * (BN / 4);
        unsigned bbits = 0;
#pragma unroll
        for (int j = 0; j < 8; j++) {
            int4 v = p[j];
            bbits |= (v.x > 0 ? 1u << (4 * j)     : 0u)
                   | (v.y > 0 ? 1u << (4 * j + 1) : 0u)
                   | (v.z > 0 ? 1u << (4 * j + 2) : 0u)
                   | (v.w > 0 ? 1u << (4 * j + 3) : 0u);
        }
        sAb[arow * 2 + ahalf] = bbits;
    }

    for (int t = t0; t < t1; t++) {
        const int buf = (t - t0) & 1;
        __syncthreads();   // prior tile's reads of sK/sV/sAb done; sQ ready (1st)

        // ---- stage K/V tile t (tf32, two layouts) ----
#pragma unroll
        for (int ii = 0; ii < 4; ii++) {
            int i   = tid + ii * NT;          // float4 index over 64x64
            int key = i >> 4;
            int d4  = (i & 15) * 4;
            float4 v = *(const float4*)&g_H[(size_t)(t * BN + key) * DD + d4];
            float tt0 = __uint_as_float(f2tf32(v.x));
            float tt1 = __uint_as_float(f2tf32(v.y));
            float tt2 = __uint_as_float(f2tf32(v.z));
            float tt3 = __uint_as_float(f2tf32(v.w));
            int kp   = perm(key);                       // for sV (k-dim perm)
            int krow = (key & ~7) | perm8(key & 7);     // for sK (n-dim perm)
            sK[krow * STRK + perm(d4)    ] = tt0;
            sK[krow * STRK + perm(d4 + 1)] = tt1;
            sK[krow * STRK + perm(d4 + 2)] = tt2;
            sK[krow * STRK + perm(d4 + 3)] = tt3;
            sV[(d4    ) * STRV + (kp ^ (((d4    ) & 7) << 3))] = tt0;
            sV[(d4 + 1) * STRV + (kp ^ (((d4 + 1) & 7) << 3))] = tt1;
            sV[(d4 + 2) * STRV + (kp ^ (((d4 + 2) & 7) << 3))] = tt2;
            sV[(d4 + 3) * STRV + (kp ^ (((d4 + 3) & 7) << 3))] = tt3;
        }
        // ---- prefetch+pack A for tile t+1 (hidden behind mma work) ----
        if (t + 1 < t1) {
            const int4* p = abase + (t + 1) * (BN / 4);
            unsigned bbits = 0;
#pragma unroll
            for (int j = 0; j < 8; j++) {
                int4 v = p[j];
                bbits |= (v.x > 0 ? 1u << (4 * j)     : 0u)
                       | (v.y > 0 ? 1u << (4 * j + 1) : 0u)
                       | (v.z > 0 ? 1u << (4 * j + 2) : 0u)
                       | (v.w > 0 ? 1u << (4 * j + 3) : 0u);
            }
            sAb[(buf ^ 1) * 256 + arow * 2 + ahalf] = bbits;
        }
        __syncthreads();   // sK/sV published; sAb[buf^1] published

        // ---- S = Q K^T (A-frags from sQ, 2x LDS.64 per ks) ----
        float sc[8][4];
#pragma unroll
        for (int na = 0; na < 8; na++)
#pragma unroll
            for (int j = 0; j < 4; j++) sc[na][j] = 0.0f;
#pragma unroll
        for (int ks = 0; ks < 8; ks++) {
            float2 qa = *(const float2*)&sQ[lrow0 * STRK + ks * 8 + 2 * lc];
            float2 qb = *(const float2*)&sQ[(lrow0 + 8) * STRK + ks * 8 + 2 * lc];
            unsigned a0 = __float_as_uint(qa.x);
            unsigned a1 = __float_as_uint(qb.x);
            unsigned a2 = __float_as_uint(qa.y);
            unsigned a3 = __float_as_uint(qb.y);
#pragma unroll
            for (int na = 0; na < 8; na++) {
                float2 bf = *(const float2*)&sK[(na * 8 + lr) * STRK + ks * 8 + 2 * lc];
                mma_tf32(sc[na], a0, a1, a2, a3,
                         __float_as_uint(bf.x), __float_as_uint(bf.y));
            }
        }

        // ---- mask to NEG_BIG ----
        {
            unsigned b0w0 = sAb[buf * 256 + lrow0 * 2];
            unsigned b0w1 = sAb[buf * 256 + lrow0 * 2 + 1];
            unsigned b1w0 = sAb[buf * 256 + (lrow0 + 8) * 2];
            unsigned b1w1 = sAb[buf * 256 + (lrow0 + 8) * 2 + 1];
#pragma unroll
            for (int na = 0; na < 8; na++) {
                unsigned m0w = (na < 4) ? b0w0 : b0w1;
                unsigned m1w = (na < 4) ? b1w0 : b1w1;
                int sh = ((na & 3) << 3) + lc;
                sc[na][0] = ((m0w >> sh)       & 1) ? sc[na][0] : NEG_BIG;
                sc[na][1] = ((m0w >> (sh + 4)) & 1) ? sc[na][1] : NEG_BIG;
                sc[na][2] = ((m1w >> sh)       & 1) ? sc[na][2] : NEG_BIG;
                sc[na][3] = ((m1w >> (sh + 4)) & 1) ? sc[na][3] : NEG_BIG;
            }
        }

        // ---- online softmax; sc becomes the P A-fragments in place ----
        {
            float mt0 = NEG_BIG, mt1 = NEG_BIG;
#pragma unroll
            for (int na = 0; na < 8; na++) {
                mt0 = fmaxf(mt0, fmaxf(sc[na][0], sc[na][1]));
                mt1 = fmaxf(mt1, fmaxf(sc[na][2], sc[na][3]));
            }
            mt0 = fmaxf(mt0, __shfl_xor_sync(0xffffffffu, mt0, 1));
            mt0 = fmaxf(mt0, __shfl_xor_sync(0xffffffffu, mt0, 2));
            mt1 = fmaxf(mt1, __shfl_xor_sync(0xffffffffu, mt1, 1));
            mt1 = fmaxf(mt1, __shfl_xor_sync(0xffffffffu, mt1, 2));

            float mn0 = fmaxf(m0, mt0), mn1 = fmaxf(m1, mt1);
            float scl0 = __expf(m0 - mn0), scl1 = __expf(m1 - mn1);
            m0 = mn0; m1 = mn1;

            float s0 = 0.0f, s1 = 0.0f;
#pragma unroll
            for (int na = 0; na < 8; na++) {
                float p00 = __expf(sc[na][0] - m0);
                float p01 = __expf(sc[na][1] - m0);
                float p10 = __expf(sc[na][2] - m1);
                float p11 = __expf(sc[na][3] - m1);
                s0 += p00 + p01;
                s1 += p10 + p11;
                sc[na][0] = __uint_as_float(f2tf32(p00));
                sc[na][1] = __uint_as_float(f2tf32(p01));
                sc[na][2] = __uint_as_float(f2tf32(p10));
                sc[na][3] = __uint_as_float(f2tf32(p11));
            }
            s0 += __shfl_xor_sync(0xffffffffu, s0, 1);
            s0 += __shfl_xor_sync(0xffffffffu, s0, 2);
            s1 += __shfl_xor_sync(0xffffffffu, s1, 1);
            s1 += __shfl_xor_sync(0xffffffffu, s1, 2);
            l0 = l0 * scl0 + s0;
            l1 = l1 * scl1 + s1;

#pragma unroll
            for (int na = 0; na < 8; na++) {
                oc[na][0] *= scl0; oc[na][1] *= scl0;
                oc[na][2] *= scl1; oc[na][3] *= scl1;
            }
        }

        // ---- O += P V (P direct from registers) ----
#pragma unroll
        for (int ks = 0; ks < 8; ks++) {
            unsigned a0 = __float_as_uint(sc[ks][0]);   // (lr,   k)
            unsigned a1 = __float_as_uint(sc[ks][2]);   // (lr+8, k)
            unsigned a2 = __float_as_uint(sc[ks][1]);   // (lr,   k+4)
            unsigned a3 = __float_as_uint(sc[ks][3]);   // (lr+8, k+4)
#pragma unroll
            for (int na = 0; na < 8; na++) {
                float2 bf = *(const float2*)&sV[(na * 8 + lr) * STRV + (((ks ^ lr) << 3) + 2 * lc)];
                mma_tf32(oc[na], a0, a1, a2, a3,
                         __float_as_uint(bf.x), __float_as_uint(bf.y));
            }
        }
    }

    // ---- write partials ----
    float* Op = g_Op + (size_t)split * NN * DD;
#pragma unroll
    for (int na = 0; na < 8; na++) {
        int c0 = na * 8 + 2 * lc;
        *(float2*)&Op[(size_t)r0 * DD + c0]       = make_float2(oc[na][0], oc[na][1]);
        *(float2*)&Op[(size_t)(r0 + 8) * DD + c0] = make_float2(oc[na][2], oc[na][3]);
    }
    if (lc == 0) {
        g_mp[split * NN + r0]     = m0;
        g_mp[split * NN + r0 + 8] = m1;
        g_lp[split * NN + r0]     = l0;
        g_lp[split * NN + r0 + 8] = l1;
    }
}

// ---------------------------------------------------------------------------
// Kernel 3: m-aware merge of the 4 split partials, normalize, relu.
// ---------------------------------------------------------------------------
__global__ void merge_kernel(float* __restrict__ Out) {
    int idx = blockIdx.x * 256 + threadIdx.x;      // over NN*DD
    int row = idx >> 6;
    float ma = g_mp[row], mb = g_mp[NN + row];
    float mc = g_mp[2 * NN + row], md = g_mp[3 * NN + row];
    float M = fmaxf(fmaxf(ma, mb), fmaxf(mc, md));
    float w0 = __expf(ma - M), w1 = __expf(mb - M);
    float w2 = __expf(mc - M), w3 = __expf(md - M);
    float denom = w0 * g_lp[row] + w1 * g_lp[NN + row]
                + w2 * g_lp[2 * NN + row] + w3 * g_lp[3 * NN + row];
    float num = w0 * g_Op[idx] + w1 * g_Op[NN * DD + idx]
              + w2 * g_Op[2 * NN * DD + idx] + w3 * g_Op[3 * NN * DD + idx];
    Out[idx] = fmaxf(num / denom, 0.0f);
}

// ---------------------------------------------------------------------------
extern "C" void kernel_launch(void* const* d_in, const int* in_sizes, int n_in,
                              void* d_out, int out_size) {
    const float* X = (const float*)d_in[0];
    const int*   A = (const int*)  d_in[1];
    const float* W = (const float*)d_in[2];
    const float* b = (const float*)d_in[3];
    float* Out = (float*)d_out;

    const int smem_bytes = (BM * STRK + BN * STRK + DD * STRV) * 4
                         + 2 * 128 * 2 * 4;   // 36864+18432+17408+2048 = 74752
    static bool attr_set = false;
    if (!attr_set) {
        cudaFuncSetAttribute(flash_mma,
                             cudaFuncAttributeMaxDynamicSharedMemorySize,
                             smem_bytes);
        attr_set = true;
    }

    h_kernel<<<NN / 8, 256>>>(X, W, b);
    flash_mma<<<SPLITS * 64, NT, smem_bytes>>>(A);
    merge_kernel<<<NN * DD / 256, 256>>>(Out);
}